// round 1
// baseline (speedup 1.0000x reference)
#include <cuda_runtime.h>
#include <cuda_bf16.h>
#include <math.h>

// ---- fixed problem shapes ----
#define B_DIM 8
#define L_DIM 1024
#define C_DIM 512
#define NP    1243            // pooled tokens: 441+256+169+121+256
#define NTOK  2267            // NP + L
#define NH    8
#define HD    64
#define LN_EPS 1e-5f

// token offsets within the 1243 pooled tokens
#define OFF_S1 0
#define OFF_S2 441
#define OFF_S3 697
#define OFF_S4 866
#define OFF_MX 987

// ---- static device scratch (no allocations allowed) ----
__device__ float g_P0[B_DIM * NP * C_DIM];     // pooled, pre-conv
__device__ float g_P1[B_DIM * NP * C_DIM];     // post conv-residual
__device__ float g_P2[B_DIM * NP * C_DIM];     // post layernorm
__device__ float g_Q [B_DIM * L_DIM * C_DIM];  // q = m @ Wq
__device__ float g_KV[B_DIM * NTOK * 2 * C_DIM];
__device__ float g_O [B_DIM * L_DIM * C_DIM];  // attention output (pre-Wp)

// =====================================================================
// Adaptive average pooling for the 4 avg branches (n = 21,16,13,11).
// grid: (987, B), block: 512 threads (one per channel).
// x layout: [B, H*W, C] with C contiguous -> coalesced reads over c.
// =====================================================================
__global__ void pool_avg_kernel(const float* __restrict__ x, float* __restrict__ P0)
{
    int tok = blockIdx.x;       // 0..986
    int b   = blockIdx.y;
    int c   = threadIdx.x;      // 0..511

    int t = tok, n;
    if      (t < 441) { n = 21; }
    else if (t < 697) { n = 16; t -= 441; }
    else if (t < 866) { n = 13; t -= 697; }
    else              { n = 11; t -= 866; }

    int p = t / n, q = t - p * n;
    int hs = (p * 64) / n, he = ((p + 1) * 64 + n - 1) / n;
    int ws = (q * 64) / n, we = ((q + 1) * 64 + n - 1) / n;

    float s = 0.f;
    for (int h = hs; h < he; h++) {
        const float* xr = x + (((size_t)b * 4096) + (size_t)h * 64) * C_DIM + c;
        for (int w = ws; w < we; w++)
            s += xr[(size_t)w * C_DIM];
    }
    float inv = 1.f / (float)((he - hs) * (we - ws));
    P0[((size_t)b * NP + tok) * C_DIM + c] = s * inv;
}

// =====================================================================
// Exact 16x16 max pool (4x4 windows). grid: (256, B), block 512.
// =====================================================================
__global__ void pool_max_kernel(const float* __restrict__ x, float* __restrict__ P0)
{
    int t = blockIdx.x;         // 0..255
    int b = blockIdx.y;
    int c = threadIdx.x;

    int p = t >> 4, q = t & 15;
    float mx = -1e30f;
    for (int h = p * 4; h < p * 4 + 4; h++) {
        const float* xr = x + (((size_t)b * 4096) + (size_t)h * 64) * C_DIM + c;
        for (int w = q * 4; w < q * 4 + 4; w++)
            mx = fmaxf(mx, xr[(size_t)w * C_DIM]);
    }
    P0[((size_t)b * NP + OFF_MX + t) * C_DIM + c] = mx;
}

// =====================================================================
// Generic 64x64 tiled SGEMM (K = 512), 256 threads, 4x4 per thread.
//   mode 0: C[r,:] = A[r,:] @ Bw (+ bias)            (rows contiguous)
//   mode 1: conv-residual: rows gathered per-branch from P0 (base A);
//           out = acc + bias + A_row ; scattered into g_P1
//   mode 2: kv gather: rows 0..NP-1 from A (=P2), rest from A2 (=m);
//           out = acc (N = 1024)
// =====================================================================
__global__ void gemm64(const float* __restrict__ A, const float* __restrict__ Bw,
                       const float* __restrict__ bias, const float* __restrict__ A2,
                       float* __restrict__ Cout,
                       int M, int N, int mode, int npix, int tok_off)
{
    const int K = 512;
    __shared__ float As[16][64];   // transposed: As[k][row]
    __shared__ float Bs[16][64];

    int tid  = threadIdx.x;
    int brow = blockIdx.y * 64;
    int bcol = blockIdx.x * 64;

    int la_row = tid >> 2;          // 0..63
    int la_k   = (tid & 3) * 4;     // 0,4,8,12
    int lb_k   = tid >> 4;          // 0..15
    int lb_n   = (tid & 15) * 4;

    int arow = brow + la_row;
    bool ok  = (arow < M);
    const float* Abase = A;
    size_t aoff = 0;
    if (ok) {
        if (mode == 0) {
            aoff = (size_t)arow * K;
        } else if (mode == 1) {
            int b = arow / npix; int t = arow - b * npix;
            aoff = ((size_t)b * NP + tok_off + t) * (size_t)C_DIM;
        } else {
            int b = arow / NTOK; int t = arow - b * NTOK;
            if (t < NP) aoff = ((size_t)b * NP + t) * (size_t)C_DIM;
            else { Abase = A2; aoff = ((size_t)b * L_DIM + (t - NP)) * (size_t)C_DIM; }
        }
    }

    float acc[4][4] = {};
    int ty = tid >> 4, tx = tid & 15;

    for (int k0 = 0; k0 < K; k0 += 16) {
        float4 av = ok ? *(const float4*)(Abase + aoff + k0 + la_k)
                       : make_float4(0.f, 0.f, 0.f, 0.f);
        As[la_k + 0][la_row] = av.x;
        As[la_k + 1][la_row] = av.y;
        As[la_k + 2][la_row] = av.z;
        As[la_k + 3][la_row] = av.w;
        *(float4*)&Bs[lb_k][lb_n] =
            *(const float4*)(Bw + (size_t)(k0 + lb_k) * N + bcol + lb_n);
        __syncthreads();

#pragma unroll
        for (int kk = 0; kk < 16; kk++) {
            float a[4], bb[4];
            *(float4*)a  = *(const float4*)&As[kk][ty * 4];
            *(float4*)bb = *(const float4*)&Bs[kk][tx * 4];
#pragma unroll
            for (int i = 0; i < 4; i++)
#pragma unroll
                for (int j = 0; j < 4; j++)
                    acc[i][j] += a[i] * bb[j];
        }
        __syncthreads();
    }

    int col = bcol + tx * 4;
#pragma unroll
    for (int i = 0; i < 4; i++) {
        int r = brow + ty * 4 + i;
        if (r >= M) continue;
        float4 o;
        o.x = acc[i][0]; o.y = acc[i][1]; o.z = acc[i][2]; o.w = acc[i][3];
        if (mode == 1) {
            int b = r / npix; int t = r - b * npix;
            size_t g = ((size_t)b * NP + tok_off + t) * (size_t)C_DIM;
            float4 res = *(const float4*)&A[g + col];
            o.x += res.x + bias[col + 0];
            o.y += res.y + bias[col + 1];
            o.z += res.z + bias[col + 2];
            o.w += res.w + bias[col + 3];
            *(float4*)&Cout[g + col] = o;
        } else {
            if (bias) {
                o.x += bias[col + 0]; o.y += bias[col + 1];
                o.z += bias[col + 2]; o.w += bias[col + 3];
            }
            *(float4*)&Cout[(size_t)r * N + col] = o;
        }
    }
}

// =====================================================================
// Copy the mx branch (pre-LN, post conv-res) to d_out[B,C,16,16].
// =====================================================================
__global__ void mx_copy_kernel(const float* __restrict__ P1, float* __restrict__ out2)
{
    int idx = blockIdx.x * blockDim.x + threadIdx.x;
    if (idx >= B_DIM * C_DIM * 256) return;
    int t = idx & 255;
    int c = (idx >> 8) & 511;
    int b = idx >> 17;
    out2[idx] = P1[(((size_t)b * NP) + OFF_MX + t) * C_DIM + c];
}

// =====================================================================
// LayerNorm over C=512. One block (128 threads, float4 each) per token.
// =====================================================================
__global__ void ln_kernel(const float* __restrict__ X, const float* __restrict__ g,
                          const float* __restrict__ be, float* __restrict__ Y)
{
    int row = blockIdx.x;
    int tid = threadIdx.x;                 // 0..127
    const float4* xr = (const float4*)(X + (size_t)row * C_DIM);
    float4 v = xr[tid];
    float s  = v.x + v.y + v.z + v.w;
    float s2 = v.x * v.x + v.y * v.y + v.z * v.z + v.w * v.w;
#pragma unroll
    for (int o = 16; o >= 1; o >>= 1) {
        s  += __shfl_xor_sync(0xffffffffu, s,  o);
        s2 += __shfl_xor_sync(0xffffffffu, s2, o);
    }
    __shared__ float ws[4], ws2[4];
    int wid = tid >> 5, lane = tid & 31;
    if (lane == 0) { ws[wid] = s; ws2[wid] = s2; }
    __syncthreads();
    float ts  = ws[0]  + ws[1]  + ws[2]  + ws[3];
    float ts2 = ws2[0] + ws2[1] + ws2[2] + ws2[3];
    float mean = ts * (1.f / C_DIM);
    float var  = ts2 * (1.f / C_DIM) - mean * mean;
    float rstd = rsqrtf(var + LN_EPS);
    float4 gg = ((const float4*)g)[tid];
    float4 bb = ((const float4*)be)[tid];
    float4 o;
    o.x = (v.x - mean) * rstd * gg.x + bb.x;
    o.y = (v.y - mean) * rstd * gg.y + bb.y;
    o.z = (v.z - mean) * rstd * gg.z + bb.z;
    o.w = (v.w - mean) * rstd * gg.w + bb.w;
    ((float4*)(Y + (size_t)row * C_DIM))[tid] = o;
}

// =====================================================================
// Fused attention: per (b, h, 64-query tile), flash-style over 36 key
// tiles of 64. 256 threads, each owns a 4x4 patch of the 64x64 S tile
// and a 4(row)x4(dim) patch of the output accumulator.
// smem: Qs[64][64], KsT[64][68] (d-major, reused for P), Vs[64][64].
// =====================================================================
#define ATT_SMEM ((64 * 64 + 64 * 68 + 64 * 64) * 4)

__global__ void attn_kernel(const float* __restrict__ Q, const float* __restrict__ KV,
                            float* __restrict__ O)
{
    extern __shared__ float sm[];
    float* Qs  = sm;                 // [64][64]
    float* KsT = sm + 64 * 64;       // [64][68], d-major; reused as P[r][c]
    float* Vs  = KsT + 64 * 68;      // [64][64]

    int tid = threadIdx.x;
    int b = blockIdx.z, h = blockIdx.y, l0 = blockIdx.x * 64;
    int ty = tid >> 4, tx = tid & 15;

    // load Q tile [64 rows][64 dims]
#pragma unroll
    for (int it = 0; it < 4; it++) {
        int row  = (tid >> 4) + it * 16;
        int col4 = (tid & 15) * 4;
        float4 v = *(const float4*)&Q[(((size_t)b * L_DIM) + l0 + row) * C_DIM + h * HD + col4];
        *(float4*)&Qs[row * 64 + col4] = v;
    }

    float acc[4][4] = {};
    float mrow[4] = {-1e30f, -1e30f, -1e30f, -1e30f};
    float lrow[4] = {0.f, 0.f, 0.f, 0.f};
    const float scale = 0.125f;   // 64^-0.5

    for (int kt = 0; kt < 36; kt++) {
        int kbase = kt * 64;
        __syncthreads();  // previous iter done reading KsT(P)/Vs; also orders Q stores

        // load K (transposed into KsT) and V (natural) for this tile
#pragma unroll
        for (int it = 0; it < 4; it++) {
            int row  = (tid >> 4) + it * 16;     // key within tile
            int col4 = (tid & 15) * 4;           // dim offset
            int kg = kbase + row;
            float4 kv4 = make_float4(0.f, 0.f, 0.f, 0.f);
            float4 vv4 = make_float4(0.f, 0.f, 0.f, 0.f);
            if (kg < NTOK) {
                size_t base = (((size_t)b * NTOK) + kg) * (size_t)(2 * C_DIM) + h * HD + col4;
                kv4 = *(const float4*)&KV[base];
                vv4 = *(const float4*)&KV[base + C_DIM];
            }
            KsT[(col4 + 0) * 68 + row] = kv4.x;
            KsT[(col4 + 1) * 68 + row] = kv4.y;
            KsT[(col4 + 2) * 68 + row] = kv4.z;
            KsT[(col4 + 3) * 68 + row] = kv4.w;
            *(float4*)&Vs[row * 64 + col4] = vv4;
        }
        __syncthreads();

        // S = Q K^T for my 4x4 patch
        float s[4][4] = {};
#pragma unroll 8
        for (int d = 0; d < 64; d++) {
            float4 kb = *(const float4*)&KsT[d * 68 + (tx << 2)];
            float q0 = Qs[(ty * 4 + 0) * 64 + d];
            float q1 = Qs[(ty * 4 + 1) * 64 + d];
            float q2 = Qs[(ty * 4 + 2) * 64 + d];
            float q3 = Qs[(ty * 4 + 3) * 64 + d];
            s[0][0] += q0 * kb.x; s[0][1] += q0 * kb.y; s[0][2] += q0 * kb.z; s[0][3] += q0 * kb.w;
            s[1][0] += q1 * kb.x; s[1][1] += q1 * kb.y; s[1][2] += q1 * kb.z; s[1][3] += q1 * kb.w;
            s[2][0] += q2 * kb.x; s[2][1] += q2 * kb.y; s[2][2] += q2 * kb.z; s[2][3] += q2 * kb.w;
            s[3][0] += q3 * kb.x; s[3][1] += q3 * kb.y; s[3][2] += q3 * kb.z; s[3][3] += q3 * kb.w;
        }

        // mask + scale, online softmax statistics (16-lane row groups)
        float tmax[4];
#pragma unroll
        for (int i = 0; i < 4; i++) {
            tmax[i] = -1e30f;
#pragma unroll
            for (int j = 0; j < 4; j++) {
                int cg = kbase + (tx << 2) + j;
                s[i][j] = (cg < NTOK) ? s[i][j] * scale : -1e30f;
                tmax[i] = fmaxf(tmax[i], s[i][j]);
            }
        }
#pragma unroll
        for (int i = 0; i < 4; i++) {
#pragma unroll
            for (int o = 8; o >= 1; o >>= 1)
                tmax[i] = fmaxf(tmax[i], __shfl_xor_sync(0xffffffffu, tmax[i], o));
        }
        float rsum[4];
#pragma unroll
        for (int i = 0; i < 4; i++) {
            float mnew  = fmaxf(mrow[i], tmax[i]);
            float alpha = __expf(mrow[i] - mnew);
            mrow[i] = mnew;
            float rs = 0.f;
#pragma unroll
            for (int j = 0; j < 4; j++) {
                float p = (s[i][j] > -1e29f) ? __expf(s[i][j] - mnew) : 0.f;
                s[i][j] = p;
                rs += p;
            }
            rsum[i] = rs;
            lrow[i] = lrow[i] * alpha;
#pragma unroll
            for (int j = 0; j < 4; j++) acc[i][j] *= alpha;
        }
#pragma unroll
        for (int i = 0; i < 4; i++) {
#pragma unroll
            for (int o = 8; o >= 1; o >>= 1)
                rsum[i] += __shfl_xor_sync(0xffffffffu, rsum[i], o);
            lrow[i] += rsum[i];
        }

        __syncthreads();  // everyone done reading KsT before P overwrite
        // write P[r][c] into KsT space (stride 68)
#pragma unroll
        for (int i = 0; i < 4; i++)
#pragma unroll
            for (int j = 0; j < 4; j++)
                KsT[(ty * 4 + i) * 68 + (tx << 2) + j] = s[i][j];
        __syncthreads();

        // O += P @ V   (my rows x my dims)
#pragma unroll 8
        for (int c = 0; c < 64; c++) {
            float4 v4 = *(const float4*)&Vs[c * 64 + (tx << 2)];
            float p0 = KsT[(ty * 4 + 0) * 68 + c];
            float p1 = KsT[(ty * 4 + 1) * 68 + c];
            float p2 = KsT[(ty * 4 + 2) * 68 + c];
            float p3 = KsT[(ty * 4 + 3) * 68 + c];
            acc[0][0] += p0 * v4.x; acc[0][1] += p0 * v4.y; acc[0][2] += p0 * v4.z; acc[0][3] += p0 * v4.w;
            acc[1][0] += p1 * v4.x; acc[1][1] += p1 * v4.y; acc[1][2] += p1 * v4.z; acc[1][3] += p1 * v4.w;
            acc[2][0] += p2 * v4.x; acc[2][1] += p2 * v4.y; acc[2][2] += p2 * v4.z; acc[2][3] += p2 * v4.w;
            acc[3][0] += p3 * v4.x; acc[3][1] += p3 * v4.y; acc[3][2] += p3 * v4.z; acc[3][3] += p3 * v4.w;
        }
    }

    // normalize + store: O[b, l, h*64 + dd]
#pragma unroll
    for (int i = 0; i < 4; i++) {
        float inv = 1.f / lrow[i];
        int row = l0 + ty * 4 + i;
        float4 o;
        o.x = acc[i][0] * inv; o.y = acc[i][1] * inv;
        o.z = acc[i][2] * inv; o.w = acc[i][3] * inv;
        *(float4*)&O[(((size_t)b * L_DIM) + row) * C_DIM + h * HD + (tx << 2)] = o;
    }
}

// =====================================================================
// launch
// =====================================================================
extern "C" void kernel_launch(void* const* d_in, const int* in_sizes, int n_in,
                              void* d_out, int out_size)
{
    const float* x    = (const float*)d_in[0];
    const float* m    = (const float*)d_in[1];
    const float* w_s1 = (const float*)d_in[2];
    const float* b_s1 = (const float*)d_in[3];
    const float* w_s2 = (const float*)d_in[4];
    const float* b_s2 = (const float*)d_in[5];
    const float* w_s3 = (const float*)d_in[6];
    const float* b_s3 = (const float*)d_in[7];
    const float* w_s4 = (const float*)d_in[8];
    const float* b_s4 = (const float*)d_in[9];
    const float* w_mx = (const float*)d_in[10];
    const float* b_mx = (const float*)d_in[11];
    const float* ln_g = (const float*)d_in[12];
    const float* ln_b = (const float*)d_in[13];
    const float* Wq   = (const float*)d_in[14];
    const float* Wkv  = (const float*)d_in[15];
    const float* Wp   = (const float*)d_in[16];
    const float* bp   = (const float*)d_in[17];
    float* out  = (float*)d_out;                       // [B,L,C]
    float* out2 = (float*)d_out + (size_t)B_DIM * L_DIM * C_DIM;  // [B,C,16,16]

    float *P0, *P1, *P2, *Qb, *KVb, *Ob;
    cudaGetSymbolAddress((void**)&P0,  g_P0);
    cudaGetSymbolAddress((void**)&P1,  g_P1);
    cudaGetSymbolAddress((void**)&P2,  g_P2);
    cudaGetSymbolAddress((void**)&Qb,  g_Q);
    cudaGetSymbolAddress((void**)&KVb, g_KV);
    cudaGetSymbolAddress((void**)&Ob,  g_O);

    static bool attr_done = false;
    if (!attr_done) {
        cudaFuncSetAttribute(attn_kernel, cudaFuncAttributeMaxDynamicSharedMemorySize, ATT_SMEM);
        attr_done = true;
    }

    // 1) pooling
    pool_avg_kernel<<<dim3(987, B_DIM), 512>>>(x, P0);
    pool_max_kernel<<<dim3(256, B_DIM), 512>>>(x, P0);

    // 2) conv-residual per branch (mode 1)
    struct { const float *w, *b; int npix, off; } br[5] = {
        { w_s1, b_s1, 441, OFF_S1 },
        { w_s2, b_s2, 256, OFF_S2 },
        { w_s3, b_s3, 169, OFF_S3 },
        { w_s4, b_s4, 121, OFF_S4 },
        { w_mx, b_mx, 256, OFF_MX },
    };
    for (int i = 0; i < 5; i++) {
        int M = B_DIM * br[i].npix;
        gemm64<<<dim3(C_DIM / 64, (M + 63) / 64), 256>>>(
            P0, br[i].w, br[i].b, nullptr, P1, M, C_DIM, 1, br[i].npix, br[i].off);
    }

    // 3) mx output (pre-LN) to d_out second chunk
    mx_copy_kernel<<<(B_DIM * C_DIM * 256 + 255) / 256, 256>>>(P1, out2);

    // 4) layernorm over pooled tokens
    ln_kernel<<<B_DIM * NP, 128>>>(P1, ln_g, ln_b, P2);

    // 5) q = m @ Wq
    gemm64<<<dim3(C_DIM / 64, (B_DIM * L_DIM) / 64), 256>>>(
        m, Wq, nullptr, nullptr, Qb, B_DIM * L_DIM, C_DIM, 0, 0, 0);

    // 6) kv = [p; m] @ Wkv   (mode 2 row gather)
    {
        int M = B_DIM * NTOK;
        gemm64<<<dim3((2 * C_DIM) / 64, (M + 63) / 64), 256>>>(
            P2, Wkv, nullptr, m, KVb, M, 2 * C_DIM, 2, 0, 0);
    }

    // 7) fused attention
    attn_kernel<<<dim3(L_DIM / 64, NH, B_DIM), 256, ATT_SMEM>>>(Qb, KVb, Ob);

    // 8) out = O @ Wp + bp
    gemm64<<<dim3(C_DIM / 64, (B_DIM * L_DIM) / 64), 256>>>(
        Ob, Wp, bp, nullptr, out, B_DIM * L_DIM, C_DIM, 0, 0, 0);
}